// round 4
// baseline (speedup 1.0000x reference)
#include <cuda_runtime.h>
#include <math.h>

#define NK 10
#define APW 544     // padded A row width (y+128 valid for y in [-128, 415])
#define CHUNK 32    // dx rows per partial-conv block
#define MAXCH 8     // ceil(255/32)

typedef unsigned long long u64;

// ---------------- scratch (static device globals; no allocation) ----------------
__device__ __align__(16) float  g_Apad[3][256][APW]; // planar A, y wrapped: [c][x][y+128]
__device__ __align__(16) float  g_Asum[256][256];
__device__ __align__(16) float  g_Kp[NK][257][512];  // packed dup kernels: [k][dx+128][2*(dy+128)+{0,1}]; row 256 = zero pad
__device__ double g_part[NK][256];
__device__ double g_ksum[NK];
__device__ int    g_rad[NK];
__device__ int    g_nch[NK];
__device__ __align__(16) float  g_pc[NK][MAXCH][256][256];  // partial conv sums (20MB)
__device__ __align__(16) float  g_U3[3][256][256];
__device__ __align__(16) float  g_mu[256*256*6];

__constant__ int c_C0[NK]  = {0,0,0,1,1,1,2,2,2,0};
__constant__ int c_grp[NK] = {0,0,0,1,1,1,2,2,2,0};

// ---------------- packed-f32x2 helpers ----------------
__device__ __forceinline__ u64 pk(float lo, float hi) {
    u64 r; asm("mov.b64 %0, {%1, %2};" : "=l"(r) : "f"(lo), "f"(hi)); return r;
}
__device__ __forceinline__ void fma2(u64 &d, u64 a, u64 b) {
    asm("fma.rn.f32x2 %0, %1, %2, %0;" : "+l"(d) : "l"(a), "l"(b));
}
__device__ __forceinline__ float2 upk(u64 v) {
    float2 f; asm("mov.b64 {%0, %1}, %2;" : "=f"(f.x), "=f"(f.y) : "l"(v)); return f;
}

// ---------------- 1. prep: planar padded A, Asum, radii ----------------
__global__ void prep_kernel(const float* __restrict__ A,
                            const float* __restrict__ R,
                            const float* __restrict__ r) {
    int x = blockIdx.x, y = threadIdx.x;
    float a0 = A[(x*256+y)*3+0];
    float a1 = A[(x*256+y)*3+1];
    float a2 = A[(x*256+y)*3+2];
    g_Asum[x][y] = a0 + a1 + a2;
    for (int j = y; j < APW; j += 256) {
        int src = (j - 128) & 255;
        float v0 = A[(x*256+src)*3+0];
        float v1 = A[(x*256+src)*3+1];
        float v2 = A[(x*256+src)*3+2];
        g_Apad[0][x][j] = v0;
        g_Apad[1][x][j] = v1;
        g_Apad[2][x][j] = v2;
    }
    if (x == 0 && y < NK) {
        // sig = 0.5*(tanh(-(Dk-1)*5)+1) underflows to exactly 0 past Dk~2.8.
        float rc = 2.85f * (R[0] + 15.0f) * r[y];
        int rad = (int)rc + 1;
        rad = max(1, min(127, rad));
        g_rad[y] = rad;
        g_nch[y] = (2*rad + 1 + CHUNK - 1) / CHUNK;
    }
}

// ---------------- 2. build packed kernels + per-row double sums ----------------
__global__ void kbuild_kernel(const float* __restrict__ R,
                              const float* __restrict__ r,
                              const float* __restrict__ a,
                              const float* __restrict__ b,
                              const float* __restrict__ w) {
    int i = blockIdx.x;   // dx + 128, or 256 = pad row
    int k = blockIdx.y;
    int j = threadIdx.x;  // dy + 128
    if (i == 256) {       // zero pad row (read by 4-tap overrun of last row)
        g_Kp[k][256][2*j]   = 0.0f;
        g_Kp[k][256][2*j+1] = 0.0f;
        return;
    }
    float fdx = (float)(i - 128);
    float fdy = (float)(j - 128);
    float D  = sqrtf(fdx*fdx + fdy*fdy);
    float Dk = D / ((R[0] + 15.0f) * r[k]);
    float ker = 0.0f;
    #pragma unroll
    for (int t = 0; t < 3; t++) {
        float d = Dk - a[k*3+t];
        ker += b[k*3+t] * expf(-d*d / w[k*3+t]);
    }
    float sig = 0.5f * (tanhf(-(Dk - 1.0f) * 5.0f) + 1.0f);
    float val = sig * ker;
    g_Kp[k][i][2*j]   = val;
    g_Kp[k][i][2*j+1] = val;

    __shared__ double sd[256];
    sd[j] = (double)val;
    __syncthreads();
    for (int s = 128; s > 0; s >>= 1) {
        if (j < s) sd[j] += sd[j + s];
        __syncthreads();
    }
    if (j == 0) g_part[k][i] = sd[0];
}

// ---------------- 3. reduce row sums -> ksum (deterministic) ----------------
__global__ void ksum_kernel() {
    int k = blockIdx.x, j = threadIdx.x;
    __shared__ double sd[256];
    sd[j] = g_part[k][j];
    __syncthreads();
    for (int s = 128; s > 0; s >>= 1) {
        if (j < s) sd[j] += sd[j + s];
        __syncthreads();
    }
    if (j == 0) g_ksum[k] = sd[0];
}

// ---------------- 4. partial circular conv (packed f32x2, dx-chunked) ----------------
// out[y] = sum_dx sum_u K[dx][u] * A[x-dx][y+u]  (K symmetric in u).
// Warp = one x-row; lane handles y = 4*lane..+3 (half L) and +128 (half H).
__global__ void __launch_bounds__(128) convp_kernel() {
    int k  = blockIdx.x;
    int ch = blockIdx.y;
    int rad = g_rad[k];
    if (ch >= g_nch[k]) return;

    int x    = blockIdx.z * 4 + threadIdx.y;
    int c    = c_C0[k];
    int lane = threadIdx.x;
    int ybL  = 128 + (lane << 2);
    int ybH  = ybL + 128;

    int dx0 = -rad + ch * CHUNK;
    int dx1 = min(rad, dx0 + CHUNK - 1);

    const float* __restrict__ Ap = &g_Apad[c][0][0];
    const float* __restrict__ Kp = &g_Kp[k][0][0];

    float tL0=0.f,tL1=0.f,tL2=0.f,tL3=0.f;
    float tH0=0.f,tH1=0.f,tH2=0.f,tH3=0.f;

    for (int dx = dx0; dx <= dx1; ++dx) {
        const float* __restrict__ Ar  = Ap + ((x - dx) & 255) * APW;
        const float* __restrict__ ArL = Ar + ybL;
        const float* __restrict__ ArH = Ar + ybH;
        const float* __restrict__ Kr  = Kp + (dx + 128) * 512 + 256;

        int rr = rad*rad - dx*dx;
        int radY = min(127, __float2int_rz(sqrtf((float)rr)) + 1);
        int us = -((radY + 3) & ~3);          // aligned start, covers [-radY, radY]

        u64 c0L=0ull, c1L=0ull, c0H=0ull, c1H=0ull;

        float4 pvL = *(const float4*)(ArL + us);
        float4 pvH = *(const float4*)(ArH + us);
        u64 P0L = pk(pvL.x, pvL.y), S0L = pk(pvL.y, pvL.z);
        u64 P0H = pk(pvH.x, pvH.y), S0H = pk(pvH.y, pvH.z);

        for (int u = us; u <= radY; u += 4) {
            ulonglong2 kA = *(const ulonglong2*)(Kr + 2*u);      // (k0,k0),(k1,k1)
            ulonglong2 kB = *(const ulonglong2*)(Kr + 2*u + 4);  // (k2,k2),(k3,k3)
            float4 nwL = *(const float4*)(ArL + u + 4);
            float4 nwH = *(const float4*)(ArH + u + 4);

            u64 P1L = pk(pvL.z, pvL.w), P2L = pk(nwL.x, nwL.y);
            u64 S1L = pk(pvL.w, nwL.x), S2L = pk(nwL.y, nwL.z);
            u64 P1H = pk(pvH.z, pvH.w), P2H = pk(nwH.x, nwH.y);
            u64 S1H = pk(pvH.w, nwH.x), S2H = pk(nwH.y, nwH.z);

            fma2(c0L, kA.x, P0L); fma2(c1L, kA.x, P1L);
            fma2(c0L, kA.y, S0L); fma2(c1L, kA.y, S1L);
            fma2(c0L, kB.x, P1L); fma2(c1L, kB.x, P2L);
            fma2(c0L, kB.y, S1L); fma2(c1L, kB.y, S2L);

            fma2(c0H, kA.x, P0H); fma2(c1H, kA.x, P1H);
            fma2(c0H, kA.y, S0H); fma2(c1H, kA.y, S1H);
            fma2(c0H, kB.x, P1H); fma2(c1H, kB.x, P2H);
            fma2(c0H, kB.y, S1H); fma2(c1H, kB.y, S2H);

            P0L = P2L; S0L = S2L; pvL = nwL;
            P0H = P2H; S0H = S2H; pvH = nwH;
        }

        float2 r0L = upk(c0L), r1L = upk(c1L);
        float2 r0H = upk(c0H), r1H = upk(c1H);
        tL0 += r0L.x; tL1 += r0L.y; tL2 += r1L.x; tL3 += r1L.y;
        tH0 += r0H.x; tH1 += r0H.y; tH2 += r1H.x; tH3 += r1H.y;
    }

    *(float4*)&g_pc[k][ch][x][ybL - 128] = make_float4(tL0, tL1, tL2, tL3);
    *(float4*)&g_pc[k][ch][x][ybH - 128] = make_float4(tH0, tH1, tH2, tH3);
}

// ---------------- 5. combine partials + growth + channel-group sums ----------------
__global__ void combine_kernel(const float* __restrict__ m,
                               const float* __restrict__ s,
                               const float* __restrict__ h) {
    int x = blockIdx.x, y = threadIdx.x;
    float u0 = 0.f, u1 = 0.f, u2 = 0.f;
    #pragma unroll
    for (int k = 0; k < NK; k++) {
        int nch = g_nch[k];
        double acc = 0.0;
        for (int ch = 0; ch < nch; ch++)
            acc += (double)g_pc[k][ch][x][y];
        float U  = (float)(acc / g_ksum[k]);
        float gg = (U - m[k]) / s[k];
        float gr = (expf(-0.5f * gg * gg) * 2.0f - 1.0f) * h[k];
        int grp = c_grp[k];
        if (grp == 0) u0 += gr;
        else if (grp == 1) u1 += gr;
        else u2 += gr;
    }
    g_U3[0][x][y] = u0;
    g_U3[1][x][y] = u1;
    g_U3[2][x][y] = u2;
}

// ---------------- 6. sobel + flow F + mu ----------------
__device__ __forceinline__ float padv(const float* p, int xx, int yy) {
    return (xx >= 0 && xx < 256 && yy >= 0 && yy < 256) ? p[xx*256 + yy] : 0.0f;
}

__global__ void sobelmu_kernel(const float* __restrict__ A) {
    int x = blockIdx.x, y = threadIdx.x;
    const float* As = &g_Asum[0][0];
    float nA0 = (padv(As,x-1,y-1) + 2.0f*padv(As,x-1,y) + padv(As,x-1,y+1))
              - (padv(As,x+1,y-1) + 2.0f*padv(As,x+1,y) + padv(As,x+1,y+1));
    float nA1 = (padv(As,x-1,y-1) + 2.0f*padv(As,x,y-1) + padv(As,x+1,y-1))
              - (padv(As,x-1,y+1) + 2.0f*padv(As,x,y+1) + padv(As,x+1,y+1));

    float px = (float)x + 0.5f;
    float py = (float)y + 0.5f;
    #pragma unroll
    for (int c = 0; c < 3; c++) {
        const float* Uc = &g_U3[c][0][0];
        float nU0 = (padv(Uc,x-1,y-1) + 2.0f*padv(Uc,x-1,y) + padv(Uc,x-1,y+1))
                  - (padv(Uc,x+1,y-1) + 2.0f*padv(Uc,x+1,y) + padv(Uc,x+1,y+1));
        float nU1 = (padv(Uc,x-1,y-1) + 2.0f*padv(Uc,x,y-1) + padv(Uc,x+1,y-1))
                  - (padv(Uc,x-1,y+1) + 2.0f*padv(Uc,x,y+1) + padv(Uc,x+1,y+1));
        float Ac = A[(x*256+y)*3 + c];
        float al = Ac * (1.0f/3.0f);
        al = al * al;
        al = fminf(al, 1.0f);
        float F0 = nU0 * (1.0f - al) - nA0 * al;
        float F1 = nU1 * (1.0f - al) - nA1 * al;
        float d0 = fminf(fmaxf(0.2f * F0, -4.35f), 4.35f);
        float d1 = fminf(fmaxf(0.2f * F1, -4.35f), 4.35f);
        float mux = fminf(fmaxf(px + d0, 0.65f), 255.35f);
        float muy = fminf(fmaxf(py + d1, 0.65f), 255.35f);
        g_mu[(x*256+y)*6 + c*2 + 0] = mux;
        g_mu[(x*256+y)*6 + c*2 + 1] = muy;
    }
}

// ---------------- 7. reintegration tracking (gather form) ----------------
__global__ void gather_kernel(float* __restrict__ out) {
    int x = blockIdx.x, y = threadIdx.x;
    float px = (float)x + 0.5f;
    float py = (float)y + 0.5f;
    float acc0 = 0.0f, acc1 = 0.0f, acc2 = 0.0f;
    const float inv = 1.0f / 1.69f;   // 1/(4*sigma^2)

    #pragma unroll
    for (int dx = -5; dx <= 5; ++dx) {
        int i = (x - dx) & 255;
        #pragma unroll
        for (int dy = -5; dy <= 5; ++dy) {
            int j = (y - dy) & 255;
            const float* mu = g_mu + (i*256 + j)*6;
            #pragma unroll
            for (int c = 0; c < 3; c++) {
                float ax = 1.15f - fabsf(px - mu[2*c + 0]);
                float ay = 1.15f - fabsf(py - mu[2*c + 1]);
                ax = fminf(fmaxf(ax, 0.0f), 1.0f);
                ay = fminf(fmaxf(ay, 0.0f), 1.0f);
                float area = ax * ay * inv;
                float av = g_Apad[c][i][j + 128];
                if (c == 0) acc0 = fmaf(av, area, acc0);
                else if (c == 1) acc1 = fmaf(av, area, acc1);
                else acc2 = fmaf(av, area, acc2);
            }
        }
    }
    out[(x*256+y)*3 + 0] = acc0;
    out[(x*256+y)*3 + 1] = acc1;
    out[(x*256+y)*3 + 2] = acc2;
}

// ---------------- launch ----------------
extern "C" void kernel_launch(void* const* d_in, const int* in_sizes, int n_in,
                              void* d_out, int out_size) {
    const float* A = (const float*)d_in[0];
    const float* R = (const float*)d_in[1];
    const float* r = (const float*)d_in[2];
    const float* m = (const float*)d_in[3];
    const float* s = (const float*)d_in[4];
    const float* h = (const float*)d_in[5];
    const float* a = (const float*)d_in[6];
    const float* b = (const float*)d_in[7];
    const float* w = (const float*)d_in[8];
    float* out = (float*)d_out;

    prep_kernel<<<256, 256>>>(A, R, r);
    kbuild_kernel<<<dim3(257, NK), 256>>>(R, r, a, b, w);
    ksum_kernel<<<NK, 256>>>();
    convp_kernel<<<dim3(NK, MAXCH, 64), dim3(32, 4)>>>();
    combine_kernel<<<256, 256>>>(m, s, h);
    sobelmu_kernel<<<256, 256>>>(A);
    gather_kernel<<<256, 256>>>(out);
}